// round 11
// baseline (speedup 1.0000x reference)
#include <cuda_runtime.h>

// Problem constants
#define B_      256
#define L_      2048
#define V_      8
#define NS_     5        // shapelets
#define BAG_    409
#define BAGP_   416      // padded (zero-filled) shapelet length in smem
#define SHIFT_  204
#define NB_     9        // windows
#define FEAT_   80       // 2*NS*V
#define NCLASS_ 10
#define BN_EPS_ 1e-5f

#define NW_      3       // windows per warp (3 groups)
#define NACC_    (NW_ * (NS_ + 1))   // 18 totals per warp
#define RSTRIDE_ 19      // odd stride -> conflict-free transpose

// Scratch
__device__ float g_feat[B_ * FEAT_];
__device__ float g_scale[FEAT_];
__device__ float g_shift[FEAT_];

#define K1_WARPS_   6                      // 2 batches x 3 window groups
#define K1_THREADS_ (K1_WARPS_ * 32)
#define RED_FLOATS_ (K1_WARPS_ * 32 * RSTRIDE_)
#define K1_DSMEM_   (RED_FLOATS_ * sizeof(float))

// ---------------------------------------------------------------------------
// Per-warp accumulation over NW_=3 windows starting at window nb0.
// Batched float4 x-loads (MLP=3); shapelet float4 streamed from smem.
// Totals land in base[0..18): [0..3)=sx2, [3 + s*3 + j]=cross(s, j).
// ---------------------------------------------------------------------------
__device__ __forceinline__ void acc_group(const float* __restrict__ xr,
                                          const float (*s_shp)[BAGP_],
                                          const int nb0,
                                          const int lane,
                                          float* base)
{
    float c[NS_][NW_];
    float sx2[NW_];
#pragma unroll
    for (int s = 0; s < NS_; s++)
#pragma unroll
        for (int j = 0; j < NW_; j++) c[s][j] = 0.f;
#pragma unroll
    for (int j = 0; j < NW_; j++) sx2[j] = 0.f;

    const float* __restrict__ xr4 = xr + (size_t)nb0 * SHIFT_ + 4 * lane;

#pragma unroll
    for (int k = 0; k < 3; k++) {
        float4 xv[NW_];
#pragma unroll
        for (int j = 0; j < NW_; j++)
            xv[j] = *(const float4*)(xr4 + j * SHIFT_ + 128 * k);

#pragma unroll
        for (int j = 0; j < NW_; j++) {
            sx2[j] = fmaf(xv[j].x, xv[j].x, sx2[j]);
            sx2[j] = fmaf(xv[j].y, xv[j].y, sx2[j]);
            sx2[j] = fmaf(xv[j].z, xv[j].z, sx2[j]);
            sx2[j] = fmaf(xv[j].w, xv[j].w, sx2[j]);
        }
#pragma unroll
        for (int s = 0; s < NS_; s++) {
            const float4 sw = *(const float4*)(&s_shp[s][128 * k + 4 * lane]);
#pragma unroll
            for (int j = 0; j < NW_; j++) {
                c[s][j] = fmaf(xv[j].x, sw.x, c[s][j]);
                c[s][j] = fmaf(xv[j].y, sw.y, c[s][j]);
                c[s][j] = fmaf(xv[j].z, sw.z, c[s][j]);
                c[s][j] = fmaf(xv[j].w, sw.w, c[s][j]);
            }
        }
    }

    // scalar tail: t = 384 + lane, valid for lane < 25
    {
        const int t = 384 + lane;
        const bool ok = (lane < 25);
        float xs[NW_];
#pragma unroll
        for (int j = 0; j < NW_; j++)
            xs[j] = ok ? xr[(size_t)(nb0 + j) * SHIFT_ + t] : 0.f;
#pragma unroll
        for (int j = 0; j < NW_; j++)
            sx2[j] = fmaf(xs[j], xs[j], sx2[j]);
#pragma unroll
        for (int s = 0; s < NS_; s++) {
            const float sv = s_shp[s][t];    // zero-padded, xs masked
#pragma unroll
            for (int j = 0; j < NW_; j++)
                c[s][j] = fmaf(xs[j], sv, c[s][j]);
        }
    }

    // ---- smem transpose reduction (per warp) ----
    float* my = base + lane * RSTRIDE_;
#pragma unroll
    for (int j = 0; j < NW_; j++) my[j] = sx2[j];
#pragma unroll
    for (int s = 0; s < NS_; s++)
#pragma unroll
        for (int j = 0; j < NW_; j++) my[NW_ + s * NW_ + j] = c[s][j];
    __syncwarp();

    float tot = 0.f;
    if (lane < NACC_) {
        float a0 = 0.f, a1 = 0.f;
#pragma unroll
        for (int l = 0; l < 32; l += 2) {
            a0 += base[l * RSTRIDE_ + lane];
            a1 += base[(l + 1) * RSTRIDE_ + lane];
        }
        tot = a0 + a1;
    }
    __syncwarp();
    if (lane < NACC_) base[lane] = tot;
}

// ---------------------------------------------------------------------------
// Kernel 1: block = (2 batches, 1 v), 3 warps per (b,v): groups of 3 windows.
// Grid 1024, 6144 warps -> 42 warps/SM, single wave at 7 blocks/SM.
// ---------------------------------------------------------------------------
__global__ __launch_bounds__(K1_THREADS_, 7)
void shapelet_feat_kernel(const float* __restrict__ x,
                          const float* __restrict__ shp,
                          float* __restrict__ feat)
{
    extern __shared__ float red[];          // [6][32][RSTRIDE_]
    __shared__ float s_shp[NS_][BAGP_];
    __shared__ float s_ss2[NS_];

    const int tid  = threadIdx.x;
    const int warp = tid >> 5;
    const int lane = tid & 31;
    const int grp  = warp % 3;              // window group 0..2
    const int bl   = warp / 3;              // batch-local 0..1
    const int v  = blockIdx.x & 7;
    const int b  = (blockIdx.x >> 3) * 2 + bl;

    // Stage shapelets (zero-pad 409..415)
    for (int i = tid; i < NS_ * BAGP_; i += K1_THREADS_) {
        const int s = i / BAGP_;
        const int t = i - s * BAGP_;
        s_shp[s][t] = (t < BAG_) ? shp[s * (V_ * BAG_) + v * BAG_ + t] : 0.f;
    }
    __syncthreads();

    // ss2[s]: warps 0..4, one shapelet each
    if (warp < NS_) {
        float q = 0.f;
        for (int t = lane; t < BAG_; t += 32) {
            const float sv = s_shp[warp][t];
            q = fmaf(sv, sv, q);
        }
#pragma unroll
        for (int o = 16; o > 0; o >>= 1) q += __shfl_xor_sync(0xffffffffu, q, o);
        if (lane == 0) s_ss2[warp] = q;
    }

    const float* __restrict__ xr = x + (size_t)b * (V_ * L_) + (size_t)v * L_;
    float* base = red + warp * (32 * RSTRIDE_);

    acc_group(xr, s_shp, grp * 3, lane, base);

    __syncthreads();                         // totals + s_ss2 visible

    // Epilogue: group-0 warp of each triplet, lanes 0..4 = shapelet s
    if (grp == 0 && lane < NS_) {
        const int s = lane;
        const float ss2v = s_ss2[s];
        float dmin = 3.402823466e+38f;
        float dsum = 0.f;
#pragma unroll
        for (int g = 0; g < 3; g++) {
            const float* bg = red + (bl * 3 + g) * (32 * RSTRIDE_);
#pragma unroll
            for (int j = 0; j < NW_; j++) {
                const float d2 = bg[j] + ss2v - 2.f * bg[NW_ + s * NW_ + j];
                const float d  = sqrtf(fmaxf(d2, 0.f));
                dmin = fminf(dmin, d);
                dsum += d;
            }
        }
        float* fout = feat + (size_t)b * FEAT_;
        fout[s * V_ + v]            = dmin;
        fout[NS_ * V_ + s * V_ + v] = dsum * (1.f / 9.f);
    }
}

// ---------------------------------------------------------------------------
// Kernel 2a: BN batch stats (two-pass). One block per feature, one thread per
// batch row. Writes scale[f] = gamma*rstd, shift[f] = beta - mu*scale.
// ---------------------------------------------------------------------------
__global__ __launch_bounds__(256, 8)
void bn_stats_kernel(const float* __restrict__ feat,
                     const float* __restrict__ gamma,
                     const float* __restrict__ beta,
                     float* __restrict__ scale,
                     float* __restrict__ shift)
{
    const int f = blockIdx.x;
    const int tid = threadIdx.x;
    __shared__ float ws[8];
    __shared__ float wq[8];

    const float v = feat[tid * FEAT_ + f];

    float s = v;
#pragma unroll
    for (int o = 16; o > 0; o >>= 1) s += __shfl_xor_sync(0xffffffffu, s, o);
    if ((tid & 31) == 0) ws[tid >> 5] = s;
    __syncthreads();

    const float mu = (ws[0] + ws[1] + ws[2] + ws[3] +
                      ws[4] + ws[5] + ws[6] + ws[7]) * (1.f / 256.f);

    const float d = v - mu;
    float q = d * d;
#pragma unroll
    for (int o = 16; o > 0; o >>= 1) q += __shfl_xor_sync(0xffffffffu, q, o);
    if ((tid & 31) == 0) wq[tid >> 5] = q;
    __syncthreads();

    if (tid == 0) {
        const float var = (wq[0] + wq[1] + wq[2] + wq[3] +
                           wq[4] + wq[5] + wq[6] + wq[7]) * (1.f / 256.f);
        const float rstd = rsqrtf(var + BN_EPS_);
        const float sc = gamma[f] * rstd;
        scale[f] = sc;
        shift[f] = beta[f] - mu * sc;
    }
}

// ---------------------------------------------------------------------------
// Kernel 2b: FC with BN folded. One block per class, one thread per batch row.
// ---------------------------------------------------------------------------
__global__ __launch_bounds__(256, 8)
void fc_kernel(const float* __restrict__ feat,
               const float* __restrict__ scale,
               const float* __restrict__ shift,
               const float* __restrict__ w,
               const float* __restrict__ fb,
               float* __restrict__ out)
{
    const int c = blockIdx.x;
    const int b = threadIdx.x;
    __shared__ float wp[FEAT_];
    __shared__ float cbias;

    if (b < FEAT_)
        wp[b] = w[c * FEAT_ + b] * scale[b];

    if (b >= 128 && b < 160) {
        // warp 4 computes the folded bias: fb[c] + sum_f shift[f]*w[c,f]
        const int lane = b - 128;
        float a = 0.f;
        for (int f = lane; f < FEAT_; f += 32)
            a = fmaf(shift[f], w[c * FEAT_ + f], a);
#pragma unroll
        for (int o = 16; o > 0; o >>= 1) a += __shfl_xor_sync(0xffffffffu, a, o);
        if (lane == 0) cbias = a + fb[c];
    }
    __syncthreads();

    const float4* __restrict__ fr = (const float4*)(feat + b * FEAT_);
    float acc = cbias;
#pragma unroll
    for (int i = 0; i < FEAT_ / 4; i++) {
        float4 xv = fr[i];
        acc = fmaf(xv.x, wp[4 * i + 0], acc);
        acc = fmaf(xv.y, wp[4 * i + 1], acc);
        acc = fmaf(xv.z, wp[4 * i + 2], acc);
        acc = fmaf(xv.w, wp[4 * i + 3], acc);
    }
    out[b * NCLASS_ + c] = acc;
}

// ---------------------------------------------------------------------------
extern "C" void kernel_launch(void* const* d_in, const int* in_sizes, int n_in,
                              void* d_out, int out_size)
{
    const float* x     = (const float*)d_in[0];  // [256, 2048, 8]
    const float* shp   = (const float*)d_in[1];  // [1, 5, 8, 409, 1]
    const float* gamma = (const float*)d_in[2];  // [80]
    const float* beta  = (const float*)d_in[3];  // [80]
    const float* fcw   = (const float*)d_in[4];  // [10, 80]
    const float* fcb   = (const float*)d_in[5];  // [10]
    float* out = (float*)d_out;                  // [256, 10]

    float *feat = nullptr, *scale = nullptr, *shift = nullptr;
    cudaGetSymbolAddress((void**)&feat,  g_feat);
    cudaGetSymbolAddress((void**)&scale, g_scale);
    cudaGetSymbolAddress((void**)&shift, g_shift);

    shapelet_feat_kernel<<<1024, K1_THREADS_, K1_DSMEM_>>>(x, shp, feat);
    bn_stats_kernel<<<FEAT_, 256>>>(feat, gamma, beta, scale, shift);
    fc_kernel<<<NCLASS_, 256>>>(feat, scale, shift, fcw, fcb, out);
}

// round 12
// speedup vs baseline: 1.0781x; 1.0781x over previous
#include <cuda_runtime.h>

// Problem constants
#define B_      256
#define L_      2048
#define V_      8
#define NS_     5        // shapelets
#define BAG_    409
#define BAGP_   416      // padded (zero-filled) shapelet length in smem
#define SHIFT_  204
#define NB_     9        // windows
#define FEAT_   80       // 2*NS*V
#define NCLASS_ 10
#define BN_EPS_ 1e-5f
#define RSTRIDE_ 33      // padded reduction row stride (conflict-free)

// Scratch
__device__ float g_feat[B_ * FEAT_];
__device__ float g_scale[FEAT_];
__device__ float g_shift[FEAT_];

#define K1_WARPS_   4                              // 2 (b,v) x 2 window-halves
#define K1_THREADS_ (K1_WARPS_ * 32)
#define RED_FLOATS_ (K1_WARPS_ * 32 * RSTRIDE_)
#define K1_DSMEM_   (RED_FLOATS_ * sizeof(float))

// ---------------------------------------------------------------------------
// Per-warp accumulation over NW windows starting at window NB0.
// Batched float4 x-loads (MLP=NW), shapelet float4 streamed from smem.
// Totals land in base[0 .. NW*(NS+1)):
//   [0..NW) = sx2 per window, [NW + s*NW + j] = cross(s, window j).
// ---------------------------------------------------------------------------
template<int NW, int NB0>
__device__ __forceinline__ void acc_half(const float* __restrict__ xr,
                                         const float (*s_shp)[BAGP_],
                                         const int lane,
                                         float* base)
{
    float c[NS_][NW];
    float sx2[NW];
#pragma unroll
    for (int s = 0; s < NS_; s++)
#pragma unroll
        for (int j = 0; j < NW; j++) c[s][j] = 0.f;
#pragma unroll
    for (int j = 0; j < NW; j++) sx2[j] = 0.f;

    const float* __restrict__ xr4 = xr + 4 * lane;

#pragma unroll
    for (int k = 0; k < 3; k++) {
        float4 xv[NW];
#pragma unroll
        for (int j = 0; j < NW; j++)
            xv[j] = *(const float4*)(xr4 + (NB0 + j) * SHIFT_ + 128 * k);

#pragma unroll
        for (int j = 0; j < NW; j++) {
            sx2[j] = fmaf(xv[j].x, xv[j].x, sx2[j]);
            sx2[j] = fmaf(xv[j].y, xv[j].y, sx2[j]);
            sx2[j] = fmaf(xv[j].z, xv[j].z, sx2[j]);
            sx2[j] = fmaf(xv[j].w, xv[j].w, sx2[j]);
        }
#pragma unroll
        for (int s = 0; s < NS_; s++) {
            const float4 sw = *(const float4*)(&s_shp[s][128 * k + 4 * lane]);
#pragma unroll
            for (int j = 0; j < NW; j++) {
                c[s][j] = fmaf(xv[j].x, sw.x, c[s][j]);
                c[s][j] = fmaf(xv[j].y, sw.y, c[s][j]);
                c[s][j] = fmaf(xv[j].z, sw.z, c[s][j]);
                c[s][j] = fmaf(xv[j].w, sw.w, c[s][j]);
            }
        }
    }

    // scalar tail: t = 384 + lane, valid for lane < 25
    {
        const int t = 384 + lane;
        const bool ok = (lane < 25);
        float xs[NW];
#pragma unroll
        for (int j = 0; j < NW; j++)
            xs[j] = ok ? xr[(NB0 + j) * SHIFT_ + t] : 0.f;
#pragma unroll
        for (int j = 0; j < NW; j++)
            sx2[j] = fmaf(xs[j], xs[j], sx2[j]);
#pragma unroll
        for (int s = 0; s < NS_; s++) {
            const float sv = s_shp[s][t];    // zero-padded, xs masked
#pragma unroll
            for (int j = 0; j < NW; j++)
                c[s][j] = fmaf(xs[j], sv, c[s][j]);
        }
    }

    // ---- smem transpose reduction (per warp) ----
    float* my = base + lane * RSTRIDE_;
#pragma unroll
    for (int j = 0; j < NW; j++) my[j] = sx2[j];
#pragma unroll
    for (int s = 0; s < NS_; s++)
#pragma unroll
        for (int j = 0; j < NW; j++) my[NW + s * NW + j] = c[s][j];
    __syncwarp();

    constexpr int NACC = NW * (NS_ + 1);     // 30 or 24
    float tot = 0.f;
    if (lane < NACC) {
        float a0 = 0.f, a1 = 0.f;
#pragma unroll
        for (int l = 0; l < 32; l += 2) {
            a0 += base[l * RSTRIDE_ + lane];
            a1 += base[(l + 1) * RSTRIDE_ + lane];
        }
        tot = a0 + a1;
    }
    __syncwarp();
    if (lane < NACC) base[lane] = tot;
}

// ---------------------------------------------------------------------------
// Kernel 1: block = (2 (b,v) pairs), warp pair per (b,v): half0 -> windows
// 0..4, half1 -> windows 5..8. Grid 1024, 4096 warps, 7 blocks/SM single
// wave with a 73-register budget (no spills, unlike the 64-reg R10 cap).
// ---------------------------------------------------------------------------
__global__ __launch_bounds__(K1_THREADS_, 7)
void shapelet_feat_kernel(const float* __restrict__ x,
                          const float* __restrict__ shp,
                          float* __restrict__ feat)
{
    extern __shared__ float red[];          // [4][32][RSTRIDE_]
    __shared__ float s_shp[NS_][BAGP_];
    __shared__ float s_ss2[NS_];

    const int tid  = threadIdx.x;
    const int warp = tid >> 5;
    const int lane = tid & 31;
    const int half = warp & 1;
    const int v  = blockIdx.x & 7;
    const int b  = (blockIdx.x >> 3) * 2 + (warp >> 1);

    // Stage shapelets (zero-pad 409..415)
    for (int i = tid; i < NS_ * BAGP_; i += K1_THREADS_) {
        const int s = i / BAGP_;
        const int t = i - s * BAGP_;
        s_shp[s][t] = (t < BAG_) ? shp[s * (V_ * BAG_) + v * BAG_ + t] : 0.f;
    }
    __syncthreads();

    // ss2[s]: 4 warps cover s = warp, warp+4
    for (int s = warp; s < NS_; s += K1_WARPS_) {
        float q = 0.f;
        for (int t = lane; t < BAG_; t += 32) {
            const float sv = s_shp[s][t];
            q = fmaf(sv, sv, q);
        }
#pragma unroll
        for (int o = 16; o > 0; o >>= 1) q += __shfl_xor_sync(0xffffffffu, q, o);
        if (lane == 0) s_ss2[s] = q;
    }

    const float* __restrict__ xr = x + (size_t)b * (V_ * L_) + (size_t)v * L_;
    float* base = red + warp * (32 * RSTRIDE_);

    if (half == 0) acc_half<5, 0>(xr, s_shp, lane, base);
    else           acc_half<4, 5>(xr, s_shp, lane, base);

    __syncthreads();                         // totals + s_ss2 visible

    // Epilogue: half-0 warp of each pair, lanes 0..4 = shapelet s
    if (half == 0 && lane < NS_) {
        const int s = lane;
        const float* baseA = base;                       // windows 0..4
        const float* baseB = base + 32 * RSTRIDE_;       // partner: windows 5..8
        const float ss2v = s_ss2[s];
        float dmin = 3.402823466e+38f;
        float dsum = 0.f;
#pragma unroll
        for (int j = 0; j < 5; j++) {
            const float d2 = baseA[j] + ss2v - 2.f * baseA[5 + s * 5 + j];
            const float d  = sqrtf(fmaxf(d2, 0.f));
            dmin = fminf(dmin, d);
            dsum += d;
        }
#pragma unroll
        for (int j = 0; j < 4; j++) {
            const float d2 = baseB[j] + ss2v - 2.f * baseB[4 + s * 4 + j];
            const float d  = sqrtf(fmaxf(d2, 0.f));
            dmin = fminf(dmin, d);
            dsum += d;
        }
        float* fout = feat + (size_t)b * FEAT_;
        fout[s * V_ + v]            = dmin;
        fout[NS_ * V_ + s * V_ + v] = dsum * (1.f / 9.f);
    }
}

// ---------------------------------------------------------------------------
// Kernel 2a: BN batch stats (two-pass). One block per feature, one thread per
// batch row. Writes scale[f] = gamma*rstd, shift[f] = beta - mu*scale.
// ---------------------------------------------------------------------------
__global__ __launch_bounds__(256, 8)
void bn_stats_kernel(const float* __restrict__ feat,
                     const float* __restrict__ gamma,
                     const float* __restrict__ beta,
                     float* __restrict__ scale,
                     float* __restrict__ shift)
{
    const int f = blockIdx.x;
    const int tid = threadIdx.x;
    __shared__ float ws[8];
    __shared__ float wq[8];

    const float v = feat[tid * FEAT_ + f];

    float s = v;
#pragma unroll
    for (int o = 16; o > 0; o >>= 1) s += __shfl_xor_sync(0xffffffffu, s, o);
    if ((tid & 31) == 0) ws[tid >> 5] = s;
    __syncthreads();

    const float mu = (ws[0] + ws[1] + ws[2] + ws[3] +
                      ws[4] + ws[5] + ws[6] + ws[7]) * (1.f / 256.f);

    const float d = v - mu;
    float q = d * d;
#pragma unroll
    for (int o = 16; o > 0; o >>= 1) q += __shfl_xor_sync(0xffffffffu, q, o);
    if ((tid & 31) == 0) wq[tid >> 5] = q;
    __syncthreads();

    if (tid == 0) {
        const float var = (wq[0] + wq[1] + wq[2] + wq[3] +
                           wq[4] + wq[5] + wq[6] + wq[7]) * (1.f / 256.f);
        const float rstd = rsqrtf(var + BN_EPS_);
        const float sc = gamma[f] * rstd;
        scale[f] = sc;
        shift[f] = beta[f] - mu * sc;
    }
}

// ---------------------------------------------------------------------------
// Kernel 2b: FC with BN folded. One block per class, one thread per batch row.
// ---------------------------------------------------------------------------
__global__ __launch_bounds__(256, 8)
void fc_kernel(const float* __restrict__ feat,
               const float* __restrict__ scale,
               const float* __restrict__ shift,
               const float* __restrict__ w,
               const float* __restrict__ fb,
               float* __restrict__ out)
{
    const int c = blockIdx.x;
    const int b = threadIdx.x;
    __shared__ float wp[FEAT_];
    __shared__ float cbias;

    if (b < FEAT_)
        wp[b] = w[c * FEAT_ + b] * scale[b];

    if (b >= 128 && b < 160) {
        // warp 4 computes the folded bias: fb[c] + sum_f shift[f]*w[c,f]
        const int lane = b - 128;
        float a = 0.f;
        for (int f = lane; f < FEAT_; f += 32)
            a = fmaf(shift[f], w[c * FEAT_ + f], a);
#pragma unroll
        for (int o = 16; o > 0; o >>= 1) a += __shfl_xor_sync(0xffffffffu, a, o);
        if (lane == 0) cbias = a + fb[c];
    }
    __syncthreads();

    const float4* __restrict__ fr = (const float4*)(feat + b * FEAT_);
    float acc = cbias;
#pragma unroll
    for (int i = 0; i < FEAT_ / 4; i++) {
        float4 xv = fr[i];
        acc = fmaf(xv.x, wp[4 * i + 0], acc);
        acc = fmaf(xv.y, wp[4 * i + 1], acc);
        acc = fmaf(xv.z, wp[4 * i + 2], acc);
        acc = fmaf(xv.w, wp[4 * i + 3], acc);
    }
    out[b * NCLASS_ + c] = acc;
}

// ---------------------------------------------------------------------------
extern "C" void kernel_launch(void* const* d_in, const int* in_sizes, int n_in,
                              void* d_out, int out_size)
{
    const float* x     = (const float*)d_in[0];  // [256, 2048, 8]
    const float* shp   = (const float*)d_in[1];  // [1, 5, 8, 409, 1]
    const float* gamma = (const float*)d_in[2];  // [80]
    const float* beta  = (const float*)d_in[3];  // [80]
    const float* fcw   = (const float*)d_in[4];  // [10, 80]
    const float* fcb   = (const float*)d_in[5];  // [10]
    float* out = (float*)d_out;                  // [256, 10]

    float *feat = nullptr, *scale = nullptr, *shift = nullptr;
    cudaGetSymbolAddress((void**)&feat,  g_feat);
    cudaGetSymbolAddress((void**)&scale, g_scale);
    cudaGetSymbolAddress((void**)&shift, g_shift);

    shapelet_feat_kernel<<<1024, K1_THREADS_, K1_DSMEM_>>>(x, shp, feat);
    bn_stats_kernel<<<FEAT_, 256>>>(feat, gamma, beta, scale, shift);
    fc_kernel<<<NCLASS_, 256>>>(feat, scale, shift, fcw, fcb, out);
}